// round 14
// baseline (speedup 1.0000x reference)
#include <cuda_runtime.h>
#include <cuda_bf16.h>

// Problem dims (fixed by the reference):
// B=2, G=8, D=32, H=128, W=160, NEIGH=9 (3x3), PAD1=2, PAD2=4
#define B_  2
#define G_  8
#define D_  32
#define H_  128
#define W_  160
#define HW_ (H_*W_)          // 20480
#define DHW_ (D_*HW_)        // 655360
#define N1_ (B_*DHW_)        // 1310720  (sim / output elements)
#define PW_ 168              // padded sim row: 4 reflected cols each side

typedef unsigned long long u64;

// x-padded similarity map (B, D, H, PW_) fp32 = 5.5 MB
__device__ float g_simp[B_*D_*H_*PW_];

// ---------------------------------------------------------------------------
// Packed f32x2 helpers (Blackwell sm_103a)
// ---------------------------------------------------------------------------
__device__ __forceinline__ u64 pk2(float lo, float hi) {
    u64 r; asm("mov.b64 %0, {%1, %2};" : "=l"(r) : "f"(lo), "f"(hi)); return r;
}
__device__ __forceinline__ void upk2(u64 v, float& lo, float& hi) {
    asm("mov.b64 {%0, %1}, %2;" : "=f"(lo), "=f"(hi) : "l"(v));
}
__device__ __forceinline__ u64 fma2(u64 a, u64 b, u64 c) {
    u64 d; asm("fma.rn.f32x2 %0, %1, %2, %3;" : "=l"(d) : "l"(a), "l"(b), "l"(c)); return d;
}
__device__ __forceinline__ u64 mul2(u64 a, u64 b) {
    u64 d; asm("mul.rn.f32x2 %0, %1, %2;" : "=l"(d) : "l"(a), "l"(b)); return d;
}
__device__ __forceinline__ u64 relu2(u64 v) {
    float a, b; upk2(v, a, b);
    return pk2(fmaxf(a, 0.0f), fmaxf(b, 0.0f));
}

// ---------------------------------------------------------------------------
// Kernel 1: per-pixel MLP, 4 pixels per thread, f32x2 packed math.
// (Near the f32x2 issue floor.) Stores into the x-padded sim buffer,
// materializing the 4 reflected columns on each side.
// ---------------------------------------------------------------------------
__global__ __launch_bounds__(256)
void mlp_sim_kernel(const float* __restrict__ x1,
                    const float* __restrict__ w0,
                    const float* __restrict__ bn0_scale,
                    const float* __restrict__ bn0_bias,
                    const float* __restrict__ w1,
                    const float* __restrict__ bn1_scale,
                    const float* __restrict__ bn1_bias,
                    const float* __restrict__ w_sim,
                    const float* __restrict__ b_sim)
{
    __shared__ __align__(16) u64 sw0p[16*8];   // dup2(w0[o][g]*bn0_scale[o]), g contiguous
    __shared__ __align__(16) u64 sw1p[16*8];   // dup2(w1[k][o]*bn1_scale[k]), k contiguous
    __shared__ float sb0[16];
    __shared__ float sb1[8];
    __shared__ float sws[8];
    __shared__ float sbs;

    const int t = threadIdx.x;
    if (t < 128) {
        float v = w0[t] * bn0_scale[t >> 3];     // t = o*8+g
        sw0p[t] = pk2(v, v);
    } else {
        int i = t - 128;                         // i = o*8+k
        int o = i >> 3, k = i & 7;
        float v = w1[k * 16 + o] * bn1_scale[k];
        sw1p[i] = pk2(v, v);
    }
    if (t < 16)       sb0[t] = bn0_bias[t];
    else if (t < 24)  sb1[t - 16] = bn1_bias[t - 16];
    else if (t < 32)  sws[t - 24] = w_sim[t - 24];
    else if (t == 32) sbs = b_sim[0];
    __syncthreads();

    const int idx4 = (blockIdx.x * 256 + t) * 4;     // N1_ multiple of 1024
    const int b = idx4 / DHW_;                       // 4 pixels share b
    const int base = idx4 + b * (G_ - 1) * DHW_;     // x1 flat idx of (b,g=0,pix)

    const float4* __restrict__ x4 = (const float4*)x1;

    u64 xp[2][G_];
#pragma unroll
    for (int g = 0; g < G_; g++) {
        float4 v = __ldg(&x4[(base + g * DHW_) >> 2]);
        xp[0][g] = pk2(v.x, v.y);
        xp[1][g] = pk2(v.z, v.w);
    }

    u64 h1p[2][8];
#pragma unroll
    for (int k = 0; k < 8; k++) {
        u64 bb = pk2(sb1[k], sb1[k]);
        h1p[0][k] = bb; h1p[1][k] = bb;
    }

#pragma unroll
    for (int o = 0; o < 16; o++) {
        u64 a0 = pk2(sb0[o], sb0[o]);
        u64 a1 = a0;
#pragma unroll
        for (int g = 0; g < G_; g += 2) {
            ulonglong2 wv = *(const ulonglong2*)&sw0p[o * 8 + g];  // LDS.128
            a0 = fma2(wv.x, xp[0][g],     a0);
            a1 = fma2(wv.x, xp[1][g],     a1);
            a0 = fma2(wv.y, xp[0][g + 1], a0);
            a1 = fma2(wv.y, xp[1][g + 1], a1);
        }
        a0 = relu2(a0);
        a1 = relu2(a1);
#pragma unroll
        for (int k = 0; k < 8; k += 2) {
            ulonglong2 wv = *(const ulonglong2*)&sw1p[o * 8 + k];  // LDS.128
            h1p[0][k]     = fma2(wv.x, a0, h1p[0][k]);
            h1p[1][k]     = fma2(wv.x, a1, h1p[1][k]);
            h1p[0][k + 1] = fma2(wv.y, a0, h1p[0][k + 1]);
            h1p[1][k + 1] = fma2(wv.y, a1, h1p[1][k + 1]);
        }
    }

    float s[4];
#pragma unroll
    for (int p = 0; p < 2; p++) {
        float s_lo = sbs, s_hi = sbs;
#pragma unroll
        for (int k = 0; k < 8; k++) {
            float lo, hi; upk2(h1p[p][k], lo, hi);
            s_lo = fmaf(sws[k], fmaxf(lo, 0.0f), s_lo);
            s_hi = fmaf(sws[k], fmaxf(hi, 0.0f), s_hi);
        }
        s[p * 2]     = s_lo;
        s[p * 2 + 1] = s_hi;
    }

    // ---- store into padded layout (row = d*H+h within b) ----
    const int rest = idx4 - b * DHW_;
    const int row  = rest / W_;
    const int w    = rest - row * W_;          // multiple of 4
    float* __restrict__ rowbase = g_simp + (size_t)(b * D_ * H_ + row) * PW_;
    *(float4*)(rowbase + 4 + w) = make_float4(s[0], s[1], s[2], s[3]);

    // mirror columns into the pads
    if (w == 0) {
        rowbase[3] = s[1]; rowbase[2] = s[2]; rowbase[1] = s[3];
    } else if (w == 4) {
        rowbase[0] = s[0];
    } else if (w == 152) {
        rowbase[167] = s[3];
    } else if (w == 156) {
        rowbase[166] = s[0]; rowbase[165] = s[1]; rowbase[164] = s[2];
    }
}

// ---------------------------------------------------------------------------
// Kernel 2: register-window two-scale 3x3 stencil, no edge path.
// Thread = (b, 2 d-slices, h, 4-pixel group). DT=2 doubles the grid vs R13
// (1280 blocks -> ~8.6/SM) to fix the grid-starved occupancy ncu showed.
// ---------------------------------------------------------------------------
#define DT_ 2

__device__ __forceinline__ int reflect_idx(int k, int n) {
    if (k < 0) return -k;
    if (k >= n) return 2 * n - 2 - k;
    return k;
}

__global__ __launch_bounds__(128)
void stencil_kernel(const float* __restrict__ offset,
                    const float* __restrict__ weight,
                    float* __restrict__ out)
{
    const int idx = blockIdx.x * 128 + threadIdx.x;   // 163,840 threads
    const int wq = idx % 40;
    int t1 = idx / 40;
    const int h  = t1 & 127;  t1 >>= 7;
    const int dg = t1 & 15;
    const int b  = t1 >> 4;
    const int w0 = wq * 4;
    const int d0 = dg * DT_;

    const float4* __restrict__ off4 = (const float4*)offset;
    const int obase4 = (b * 18 * HW_ + h * W_ + w0) >> 2;

    u64 acc[DT_][2];
#pragma unroll
    for (int dd = 0; dd < DT_; dd++) { acc[dd][0] = 0ULL; acc[dd][1] = 0ULL; }

    const float4* __restrict__ simp4 = (const float4*)g_simp;
    const int base4    = (((b * D_ + d0) * H_) * PW_ + w0) >> 2;
    const int dstride4 = (H_ * PW_) >> 2;             // 5376
    const int rstride4 = PW_ >> 2;                    // 42

    // rows dy = -4,-2,0,+2,+4 : wide on even i, narrow on i in {1,2,3}
#pragma unroll 1
    for (int i = 0; i < 5; i++) {
        const int dy = 2 * i - 4;
        const int gr = reflect_idx(h + dy, H_);
        const bool doN = (i >= 1) && (i <= 3);
        const bool doW = ((i & 1) == 0);

        u64 nw[3][2], ww[3][2];
        if (doN) {
            const int sr = i - 1;
#pragma unroll
            for (int tt = 0; tt < 3; tt++) {
                float4 v = __ldg(&off4[obase4 + (((9 + sr * 3 + tt) * HW_) >> 2)]);
                nw[tt][0] = pk2(v.x, v.y); nw[tt][1] = pk2(v.z, v.w);
            }
        }
        if (doW) {
            const int sr = i >> 1;
#pragma unroll
            for (int tt = 0; tt < 3; tt++) {
                float4 v = __ldg(&off4[obase4 + (((sr * 3 + tt) * HW_) >> 2)]);
                ww[tt][0] = pk2(v.x, v.y); ww[tt][1] = pk2(v.z, v.w);
            }
        }

        const float4* __restrict__ rowp = simp4 + base4 + gr * rstride4;
#pragma unroll
        for (int dd = 0; dd < DT_; dd++) {
            const float4* __restrict__ p = rowp + dd * dstride4;
            float4 A  = __ldg(p);
            float4 Bv = __ldg(p + 1);
            float4 C  = __ldg(p + 2);
            u64 W0 = pk2(A.x,  A.y),  W1 = pk2(A.z,  A.w);
            u64 W2 = pk2(Bv.x, Bv.y), W3 = pk2(Bv.z, Bv.w);
            u64 W4 = pk2(C.x,  C.y),  W5 = pk2(C.z,  C.w);
            if (doN) {
                acc[dd][0] = fma2(nw[0][0], W1, acc[dd][0]);
                acc[dd][0] = fma2(nw[1][0], W2, acc[dd][0]);
                acc[dd][0] = fma2(nw[2][0], W3, acc[dd][0]);
                acc[dd][1] = fma2(nw[0][1], W2, acc[dd][1]);
                acc[dd][1] = fma2(nw[1][1], W3, acc[dd][1]);
                acc[dd][1] = fma2(nw[2][1], W4, acc[dd][1]);
            }
            if (doW) {
                acc[dd][0] = fma2(ww[0][0], W0, acc[dd][0]);
                acc[dd][0] = fma2(ww[1][0], W2, acc[dd][0]);
                acc[dd][0] = fma2(ww[2][0], W4, acc[dd][0]);
                acc[dd][1] = fma2(ww[0][1], W1, acc[dd][1]);
                acc[dd][1] = fma2(ww[1][1], W3, acc[dd][1]);
                acc[dd][1] = fma2(ww[2][1], W5, acc[dd][1]);
            }
        }
    }

    float4 wv = __ldg(&((const float4*)weight)[(b * HW_ + h * W_ + w0) >> 2]);
    const u64 wg0 = pk2(0.5f * wv.x, 0.5f * wv.y);
    const u64 wg1 = pk2(0.5f * wv.z, 0.5f * wv.w);

#pragma unroll
    for (int dd = 0; dd < DT_; dd++) {
        u64 r0 = mul2(acc[dd][0], wg0);
        u64 r1 = mul2(acc[dd][1], wg1);
        float x0, x1, x2, x3; upk2(r0, x0, x1); upk2(r1, x2, x3);
        ((float4*)out)[((b * D_ + d0 + dd) * HW_ + h * W_ + w0) >> 2] =
            make_float4(x0, x1, x2, x3);
    }
}

// ---------------------------------------------------------------------------
// Launch
// ---------------------------------------------------------------------------
extern "C" void kernel_launch(void* const* d_in, const int* in_sizes, int n_in,
                              void* d_out, int out_size)
{
    const float* x1        = (const float*)d_in[0];
    const float* offset    = (const float*)d_in[1];
    const float* weight    = (const float*)d_in[2];
    const float* w0        = (const float*)d_in[3];
    const float* bn0_scale = (const float*)d_in[4];
    const float* bn0_bias  = (const float*)d_in[5];
    const float* w1        = (const float*)d_in[6];
    const float* bn1_scale = (const float*)d_in[7];
    const float* bn1_bias  = (const float*)d_in[8];
    const float* w_sim     = (const float*)d_in[9];
    const float* b_sim     = (const float*)d_in[10];
    float* out = (float*)d_out;

    // Kernel 1: 4 pixels/thread -> 327,680 threads, grid 1280
    mlp_sim_kernel<<<N1_ / (256 * 4), 256>>>(x1, w0, bn0_scale, bn0_bias,
                                             w1, bn1_scale, bn1_bias, w_sim, b_sim);

    // Kernel 2: B*(D/2)*H*(W/4) = 163,840 threads, grid 1280
    const int n2 = B_ * (D_ / DT_) * H_ * (W_ / 4);
    stencil_kernel<<<n2 / 128, 128>>>(offset, weight, out);
}

// round 15
// speedup vs baseline: 1.0431x; 1.0431x over previous
#include <cuda_runtime.h>
#include <cuda_bf16.h>

// Problem dims (fixed by the reference):
// B=2, G=8, D=32, H=128, W=160, NEIGH=9 (3x3), PAD1=2, PAD2=4
#define B_  2
#define G_  8
#define D_  32
#define H_  128
#define W_  160
#define HW_ (H_*W_)          // 20480
#define DHW_ (D_*HW_)        // 655360
#define N1_ (B_*DHW_)        // 1310720  (sim / output elements)
#define PW_ 168              // padded sim row: 4 reflected cols each side

typedef unsigned long long u64;

// x-padded similarity map (B, D, H, PW_) fp32 = 5.5 MB
__device__ float g_simp[B_*D_*H_*PW_];

// ---------------------------------------------------------------------------
// Packed f32x2 helpers (Blackwell sm_103a)
// ---------------------------------------------------------------------------
__device__ __forceinline__ u64 pk2(float lo, float hi) {
    u64 r; asm("mov.b64 %0, {%1, %2};" : "=l"(r) : "f"(lo), "f"(hi)); return r;
}
__device__ __forceinline__ void upk2(u64 v, float& lo, float& hi) {
    asm("mov.b64 {%0, %1}, %2;" : "=f"(lo), "=f"(hi) : "l"(v));
}
__device__ __forceinline__ u64 fma2(u64 a, u64 b, u64 c) {
    u64 d; asm("fma.rn.f32x2 %0, %1, %2, %3;" : "=l"(d) : "l"(a), "l"(b), "l"(c)); return d;
}
__device__ __forceinline__ u64 mul2(u64 a, u64 b) {
    u64 d; asm("mul.rn.f32x2 %0, %1, %2;" : "=l"(d) : "l"(a), "l"(b)); return d;
}
__device__ __forceinline__ u64 relu2(u64 v) {
    float a, b; upk2(v, a, b);
    return pk2(fmaxf(a, 0.0f), fmaxf(b, 0.0f));
}

// ---------------------------------------------------------------------------
// Kernel 1: per-pixel MLP, 4 pixels per thread, f32x2 packed math.
// (Near the f32x2 issue floor.) Stores into the x-padded sim buffer,
// materializing the 4 reflected columns on each side.
// ---------------------------------------------------------------------------
__global__ __launch_bounds__(256)
void mlp_sim_kernel(const float* __restrict__ x1,
                    const float* __restrict__ w0,
                    const float* __restrict__ bn0_scale,
                    const float* __restrict__ bn0_bias,
                    const float* __restrict__ w1,
                    const float* __restrict__ bn1_scale,
                    const float* __restrict__ bn1_bias,
                    const float* __restrict__ w_sim,
                    const float* __restrict__ b_sim)
{
    __shared__ __align__(16) u64 sw0p[16*8];   // dup2(w0[o][g]*bn0_scale[o]), g contiguous
    __shared__ __align__(16) u64 sw1p[16*8];   // dup2(w1[k][o]*bn1_scale[k]), k contiguous
    __shared__ float sb0[16];
    __shared__ float sb1[8];
    __shared__ float sws[8];
    __shared__ float sbs;

    const int t = threadIdx.x;
    if (t < 128) {
        float v = w0[t] * bn0_scale[t >> 3];     // t = o*8+g
        sw0p[t] = pk2(v, v);
    } else {
        int i = t - 128;                         // i = o*8+k
        int o = i >> 3, k = i & 7;
        float v = w1[k * 16 + o] * bn1_scale[k];
        sw1p[i] = pk2(v, v);
    }
    if (t < 16)       sb0[t] = bn0_bias[t];
    else if (t < 24)  sb1[t - 16] = bn1_bias[t - 16];
    else if (t < 32)  sws[t - 24] = w_sim[t - 24];
    else if (t == 32) sbs = b_sim[0];
    __syncthreads();

    const int idx4 = (blockIdx.x * 256 + t) * 4;     // N1_ multiple of 1024
    const int b = idx4 / DHW_;                       // 4 pixels share b
    const int base = idx4 + b * (G_ - 1) * DHW_;     // x1 flat idx of (b,g=0,pix)

    const float4* __restrict__ x4 = (const float4*)x1;

    u64 xp[2][G_];
#pragma unroll
    for (int g = 0; g < G_; g++) {
        float4 v = __ldg(&x4[(base + g * DHW_) >> 2]);
        xp[0][g] = pk2(v.x, v.y);
        xp[1][g] = pk2(v.z, v.w);
    }

    u64 h1p[2][8];
#pragma unroll
    for (int k = 0; k < 8; k++) {
        u64 bb = pk2(sb1[k], sb1[k]);
        h1p[0][k] = bb; h1p[1][k] = bb;
    }

#pragma unroll
    for (int o = 0; o < 16; o++) {
        u64 a0 = pk2(sb0[o], sb0[o]);
        u64 a1 = a0;
#pragma unroll
        for (int g = 0; g < G_; g += 2) {
            ulonglong2 wv = *(const ulonglong2*)&sw0p[o * 8 + g];  // LDS.128
            a0 = fma2(wv.x, xp[0][g],     a0);
            a1 = fma2(wv.x, xp[1][g],     a1);
            a0 = fma2(wv.y, xp[0][g + 1], a0);
            a1 = fma2(wv.y, xp[1][g + 1], a1);
        }
        a0 = relu2(a0);
        a1 = relu2(a1);
#pragma unroll
        for (int k = 0; k < 8; k += 2) {
            ulonglong2 wv = *(const ulonglong2*)&sw1p[o * 8 + k];  // LDS.128
            h1p[0][k]     = fma2(wv.x, a0, h1p[0][k]);
            h1p[1][k]     = fma2(wv.x, a1, h1p[1][k]);
            h1p[0][k + 1] = fma2(wv.y, a0, h1p[0][k + 1]);
            h1p[1][k + 1] = fma2(wv.y, a1, h1p[1][k + 1]);
        }
    }

    float s[4];
#pragma unroll
    for (int p = 0; p < 2; p++) {
        float s_lo = sbs, s_hi = sbs;
#pragma unroll
        for (int k = 0; k < 8; k++) {
            float lo, hi; upk2(h1p[p][k], lo, hi);
            s_lo = fmaf(sws[k], fmaxf(lo, 0.0f), s_lo);
            s_hi = fmaf(sws[k], fmaxf(hi, 0.0f), s_hi);
        }
        s[p * 2]     = s_lo;
        s[p * 2 + 1] = s_hi;
    }

    // ---- store into padded layout (row = d*H+h within b) ----
    const int rest = idx4 - b * DHW_;
    const int row  = rest / W_;
    const int w    = rest - row * W_;          // multiple of 4
    float* __restrict__ rowbase = g_simp + (size_t)(b * D_ * H_ + row) * PW_;
    *(float4*)(rowbase + 4 + w) = make_float4(s[0], s[1], s[2], s[3]);

    // mirror columns into the pads
    if (w == 0) {
        rowbase[3] = s[1]; rowbase[2] = s[2]; rowbase[1] = s[3];
    } else if (w == 4) {
        rowbase[0] = s[0];
    } else if (w == 152) {
        rowbase[167] = s[3];
    } else if (w == 156) {
        rowbase[166] = s[0]; rowbase[165] = s[1]; rowbase[164] = s[2];
    }
}

// ---------------------------------------------------------------------------
// Kernel 2: register-window two-scale 3x3 stencil, no edge path.
// Thread = (b, 4 d-slices, h, 8-pixel group). A 16-float row window
// (4 LDG.128) serves both scales' taps for all 8 pixels; offsets amortized
// over 4 d-slices. 100 LDG.128 per 32 outputs = 50 B/out (R13: 79).
// ---------------------------------------------------------------------------
__device__ __forceinline__ int reflect_idx(int k, int n) {
    if (k < 0) return -k;
    if (k >= n) return 2 * n - 2 - k;
    return k;
}

__global__ __launch_bounds__(64)
void stencil_kernel(const float* __restrict__ offset,
                    const float* __restrict__ weight,
                    float* __restrict__ out)
{
    const int idx = blockIdx.x * 64 + threadIdx.x;    // 40,960 threads
    const int wq = idx % 20;
    int t1 = idx / 20;
    const int h  = t1 & 127;  t1 >>= 7;
    const int dg = t1 & 7;
    const int b  = t1 >> 3;
    const int w0 = wq * 8;
    const int d0 = dg * 4;

    const float4* __restrict__ off4 = (const float4*)offset;
    const int obase4 = (b * 18 * HW_ + h * W_ + w0) >> 2;

    u64 acc[4][4];                                    // [dd][pixel-pair]
#pragma unroll
    for (int dd = 0; dd < 4; dd++)
#pragma unroll
        for (int p = 0; p < 4; p++) acc[dd][p] = 0ULL;

    const float4* __restrict__ simp4 = (const float4*)g_simp;
    const int base4    = (((b * D_ + d0) * H_) * PW_ + w0) >> 2;  // w0 mult of 8
    const int dstride4 = (H_ * PW_) >> 2;             // 5376
    const int rstride4 = PW_ >> 2;                    // 42

    // rows dy = -4,-2,0,+2,+4 : wide on even i, narrow on i in {1,2,3}
#pragma unroll 1
    for (int i = 0; i < 5; i++) {
        const int gr = reflect_idx(h + 2 * i - 4, H_);
        const bool doN = (i >= 1) && (i <= 3);
        const bool doW = ((i & 1) == 0);

        // per-tap weights for 8 pixels: 2 float4 = 4 u64 each
        u64 nw[3][4], ww[3][4];
        if (doN) {
            const int sr = i - 1;
#pragma unroll
            for (int tt = 0; tt < 3; tt++) {
                const int o4 = obase4 + (((9 + sr * 3 + tt) * HW_) >> 2);
                float4 v0 = __ldg(&off4[o4]);
                float4 v1 = __ldg(&off4[o4 + 1]);
                nw[tt][0] = pk2(v0.x, v0.y); nw[tt][1] = pk2(v0.z, v0.w);
                nw[tt][2] = pk2(v1.x, v1.y); nw[tt][3] = pk2(v1.z, v1.w);
            }
        }
        if (doW) {
            const int sr = i >> 1;
#pragma unroll
            for (int tt = 0; tt < 3; tt++) {
                const int o4 = obase4 + (((sr * 3 + tt) * HW_) >> 2);
                float4 v0 = __ldg(&off4[o4]);
                float4 v1 = __ldg(&off4[o4 + 1]);
                ww[tt][0] = pk2(v0.x, v0.y); ww[tt][1] = pk2(v0.z, v0.w);
                ww[tt][2] = pk2(v1.x, v1.y); ww[tt][3] = pk2(v1.z, v1.w);
            }
        }

        const float4* __restrict__ rowp = simp4 + base4 + gr * rstride4;
#pragma unroll
        for (int dd = 0; dd < 4; dd++) {
            const float4* __restrict__ p = rowp + dd * dstride4;
            float4 A = __ldg(p);
            float4 Bv = __ldg(p + 1);
            float4 C = __ldg(p + 2);
            float4 Dv = __ldg(p + 3);
            u64 Wu[8];
            Wu[0] = pk2(A.x,  A.y);  Wu[1] = pk2(A.z,  A.w);
            Wu[2] = pk2(Bv.x, Bv.y); Wu[3] = pk2(Bv.z, Bv.w);
            Wu[4] = pk2(C.x,  C.y);  Wu[5] = pk2(C.z,  C.w);
            Wu[6] = pk2(Dv.x, Dv.y); Wu[7] = pk2(Dv.z, Dv.w);
            // pixel pair p (actual cols w0+2p, w0+2p+1): padded center u64 = p+2
            if (doN) {
#pragma unroll
                for (int p4 = 0; p4 < 4; p4++) {
                    acc[dd][p4] = fma2(nw[0][p4], Wu[p4 + 1], acc[dd][p4]);
                    acc[dd][p4] = fma2(nw[1][p4], Wu[p4 + 2], acc[dd][p4]);
                    acc[dd][p4] = fma2(nw[2][p4], Wu[p4 + 3], acc[dd][p4]);
                }
            }
            if (doW) {
#pragma unroll
                for (int p4 = 0; p4 < 4; p4++) {
                    acc[dd][p4] = fma2(ww[0][p4], Wu[p4],     acc[dd][p4]);
                    acc[dd][p4] = fma2(ww[1][p4], Wu[p4 + 2], acc[dd][p4]);
                    acc[dd][p4] = fma2(ww[2][p4], Wu[p4 + 4], acc[dd][p4]);
                }
            }
        }
    }

    // final scaling + store (8 floats = 2 float4 per dd)
    const int wb4 = (b * HW_ + h * W_ + w0) >> 2;
    float4 wv0 = __ldg(&((const float4*)weight)[wb4]);
    float4 wv1 = __ldg(&((const float4*)weight)[wb4 + 1]);
    u64 wg[4];
    wg[0] = pk2(0.5f * wv0.x, 0.5f * wv0.y);
    wg[1] = pk2(0.5f * wv0.z, 0.5f * wv0.w);
    wg[2] = pk2(0.5f * wv1.x, 0.5f * wv1.y);
    wg[3] = pk2(0.5f * wv1.z, 0.5f * wv1.w);

#pragma unroll
    for (int dd = 0; dd < 4; dd++) {
        float r[8];
#pragma unroll
        for (int p4 = 0; p4 < 4; p4++) {
            u64 v = mul2(acc[dd][p4], wg[p4]);
            upk2(v, r[2 * p4], r[2 * p4 + 1]);
        }
        const int ob4 = ((b * D_ + d0 + dd) * HW_ + h * W_ + w0) >> 2;
        ((float4*)out)[ob4]     = make_float4(r[0], r[1], r[2], r[3]);
        ((float4*)out)[ob4 + 1] = make_float4(r[4], r[5], r[6], r[7]);
    }
}

// ---------------------------------------------------------------------------
// Launch
// ---------------------------------------------------------------------------
extern "C" void kernel_launch(void* const* d_in, const int* in_sizes, int n_in,
                              void* d_out, int out_size)
{
    const float* x1        = (const float*)d_in[0];
    const float* offset    = (const float*)d_in[1];
    const float* weight    = (const float*)d_in[2];
    const float* w0        = (const float*)d_in[3];
    const float* bn0_scale = (const float*)d_in[4];
    const float* bn0_bias  = (const float*)d_in[5];
    const float* w1        = (const float*)d_in[6];
    const float* bn1_scale = (const float*)d_in[7];
    const float* bn1_bias  = (const float*)d_in[8];
    const float* w_sim     = (const float*)d_in[9];
    const float* b_sim     = (const float*)d_in[10];
    float* out = (float*)d_out;

    // Kernel 1: 4 pixels/thread -> 327,680 threads, grid 1280
    mlp_sim_kernel<<<N1_ / (256 * 4), 256>>>(x1, w0, bn0_scale, bn0_bias,
                                             w1, bn1_scale, bn1_bias, w_sim, b_sim);

    // Kernel 2: B*(D/4)*H*(W/8) = 40,960 threads, grid 640 @ 64 threads
    const int n2 = B_ * (D_ / 4) * H_ * (W_ / 8);
    stencil_kernel<<<n2 / 64, 64>>>(offset, weight, out);
}